// round 12
// baseline (speedup 1.0000x reference)
#include <cuda_runtime.h>
#include <cstdint>

// ---------------------------------------------------------------------------
// B-spline basis (cubic, DF=16) via de Boor's algorithm.
// KNOTS = [0,0,0] ++ linspace(0, 1+1e-7, 14) ++ [1,1,1]   (fp32, numpy-exact)
// vs R11 (best): (a) FULL template — n divisible by block span, so all bounds
// checks / 64-bit limit compares are compiled out (guarded fallback kept for
// generality); (b) all indexing in int32 (max index n*4 = 16.7M) — kills
// IMAD.WIDE chains and register pairs; (c) __launch_bounds__(256,7) restores
// occupancy (regs 40 -> <=36, 6 -> 7 CTAs/SM). Rotated-slot smem layout kept:
// both STS.128 scatter and LDS.128 copy-out are bank-conflict-free.
// ---------------------------------------------------------------------------

#define STEP_D (1.0000001 / 13.0)
#define KP(i)  ((float)((double)(i) * STEP_D))

__constant__ float KN[20] = {
    0.0f, 0.0f, 0.0f,
    0.0f,                                   // KN[3]  = linspace[0]
    KP(1),  KP(2),  KP(3),  KP(4),  KP(5),  KP(6),
    KP(7),  KP(8),  KP(9),  KP(10), KP(11), KP(12),
    (float)1.0000001,                       // KN[16] = linspace endpoint (exact stop)
    1.0f, 1.0f, 1.0f
};

#define INV_H ((float)(13.0 / 1.0000001))

#define TPB   256
#define NW    (TPB / 32)
#define TILES 8                 // elements per block = 2048

template<bool FULL>
__global__ __launch_bounds__(TPB, 7) void bspline_kernel(
    const float* __restrict__ ts,
    float4* __restrict__ out4,
    int n)
{
    __shared__ float sKN[20];
    __shared__ __align__(128) float4 sT[NW][32 * 4];   // dense 2KB per warp slab

    const int tid  = threadIdx.x;
    const int wid  = tid >> 5;
    const int lane = tid & 31;

    if (tid < 20) sKN[tid] = KN[tid];

    float4* wbuf = sT[wid];
    const int rot = (lane >> 1) & 3;        // this thread's element rotation

    const int base = blockIdx.x * (TPB * TILES);

    // Warp w's element for tile k: base + k*TPB + wid*32 + lane.
    const int egi = base + (wid << 5) + lane;
    float t;
    if (FULL) t = ts[egi];
    else      t = ts[(egi < n) ? egi : (n - 1)];

    __syncthreads();   // knots visible (only block-wide sync)

    #pragma unroll 1
    for (int k = 0; k < TILES; k++) {
        // ---- de Boor: 4 nonzero cubic basis functions, span j in [0,12] ----
        int j = (int)(t * INV_H);
        j = max(0, min(12, j));
        j -= (j > 0)  && (t <  sKN[3 + j]);
        j += (j < 12) && (t >= sKN[4 + j]);

        const int span = j + 3;
        const float l1 = t - sKN[span];
        const float l2 = t - sKN[span - 1];
        const float l3 = t - sKN[span - 2];
        const float r1 = sKN[span + 1] - t;
        const float r2 = sKN[span + 2] - t;
        const float r3 = sKN[span + 3] - t;

        float N0 = 1.0f, N1, N2, N3, sv, tp;
        tp = __fdividef(N0, r1 + l1); N0 = r1 * tp; N1 = l1 * tp;
        tp = __fdividef(N0, r1 + l2); N0 = r1 * tp; sv = l2 * tp;
        tp = __fdividef(N1, r2 + l1); N1 = sv + r2 * tp; N2 = l1 * tp;
        tp = __fdividef(N0, r1 + l3); N0 = r1 * tp; sv = l3 * tp;
        tp = __fdividef(N1, r2 + l2); N1 = sv + r2 * tp; sv = l2 * tp;
        tp = __fdividef(N2, r3 + l1); N2 = sv + r3 * tp; N3 = l1 * tp;

        // Prefetch next tile's t.
        float tn = 0.0f;
        if (k + 1 < TILES) {
            const int gn = egi + (k + 1) * TPB;
            if (FULL) tn = ts[gn];
            else      tn = ts[(gn < n) ? gn : (n - 1)];
        }

        // ---- Build the element's 16-float row as 4 float4 slots ----
        const int jq  = j >> 2;
        const int jr  = j & 3;
        const int jq1 = (jq + 1) & 3;
        // vA = row slot jq (N shifted right by jr), vB = row slot jq+1.
        const float vA0 = (jr == 0) ? N0 : 0.f;
        const float vA1 = (jr == 0) ? N1 : (jr == 1) ? N0 : 0.f;
        const float vA2 = (jr == 0) ? N2 : (jr == 1) ? N1 : (jr == 2) ? N0 : 0.f;
        const float vA3 = (jr == 0) ? N3 : (jr == 1) ? N2 : (jr == 2) ? N1 : N0;
        const float vB0 = (jr == 1) ? N3 : (jr == 2) ? N2 : (jr == 3) ? N1 : 0.f;
        const float vB1 = (jr == 2) ? N3 : (jr == 3) ? N2 : 0.f;
        const float vB2 = (jr == 3) ? N3 : 0.f;

        // Scatter: logical slot s -> physical slot (s+rot)&3. Conflict-free.
        float4* erow = wbuf + (lane << 2);
        #pragma unroll
        for (int s = 0; s < 4; s++) {
            const bool a = (s == jq);
            const bool b = (s == jq1);
            float4 v;
            v.x = a ? vA0 : b ? vB0 : 0.f;
            v.y = a ? vA1 : b ? vB1 : 0.f;
            v.z = a ? vA2 : b ? vB2 : 0.f;
            v.w = a ? vA3 : 0.f;            // vB3 == 0
            erow[(s + rot) & 3] = v;
        }

        __syncwarp();

        // ---- Copy-out: 128 contiguous float4s, CF LDS.128 + streaming STG ----
        const int tbase4 = (base + k * TPB + (wid << 5)) * 4;  // float4 units
        float4* ob = out4 + tbase4;
        #pragma unroll
        for (int i = 0; i < 4; i++) {
            const int f  = lane + 32 * i;
            const int e  = f >> 2;
            const int c  = f & 3;
            const int re = (e >> 1) & 3;
            const float4 v = wbuf[(e << 2) + ((c + re) & 3)];
            if (FULL || tbase4 + f < n * 4)
                __stcs(&ob[f], v);
        }

        __syncwarp();   // slab reads done before next tile's scatter

        t = tn;
    }
}

extern "C" void kernel_launch(void* const* d_in, const int* in_sizes, int n_in,
                              void* d_out, int out_size)
{
    const float* ts = (const float*)d_in[0];
    float4* out4 = (float4*)d_out;
    const int n = in_sizes[0];           // 32 * 131072 = 4194304 elements
    const int epb = TPB * TILES;
    const int blocks = (n + epb - 1) / epb;
    if (n % epb == 0)
        bspline_kernel<true><<<blocks, TPB>>>(ts, out4, n);
    else
        bspline_kernel<false><<<blocks, TPB>>>(ts, out4, n);
}

// round 13
// speedup vs baseline: 1.0529x; 1.0529x over previous
#include <cuda_runtime.h>
#include <cstdint>

// ---------------------------------------------------------------------------
// B-spline basis (cubic, DF=16) via de Boor's algorithm.
// KNOTS = [0,0,0] ++ linspace(0, 1+1e-7, 14) ++ [1,1,1]   (fp32, numpy-exact)
// vs R11 (best, 43.5us):
//  * knots computed arithmetically (m*step, clamped) instead of divergent
//    shared-memory lookups: removes 8 LDS.32 per element (40% of MIO ops) and
//    a 29-cyc LDS latency at the head of the de Boor chain. <=1ulp knot
//    perturbation -> ~1e-7 output change (tolerance 1e-3; basis continuous).
//  * FULL template (n divisible by block span: all bounds checks compiled
//    out) + int32 indexing. NO register cap (R12 showed the cap hurts).
// Rotated-slot smem layout kept: STS.128 scatter and LDS.128 copy-out both
// bank-conflict-free. Warp-autonomous tiles, __syncwarp only, __stcs stores.
// ---------------------------------------------------------------------------

#define STEP_D (1.0000001 / 13.0)
#define STEPF  ((float)STEP_D)
#define INV_H  ((float)(13.0 / 1.0000001))

#define TPB   256
#define NW    (TPB / 32)
#define TILES 8                 // elements per block = 2048

template<bool FULL>
__global__ __launch_bounds__(TPB) void bspline_kernel(
    const float* __restrict__ ts,
    float4* __restrict__ out4,
    int n)
{
    __shared__ __align__(128) float4 sT[NW][32 * 4];   // dense 2KB per warp slab

    const int tid  = threadIdx.x;
    const int wid  = tid >> 5;
    const int lane = tid & 31;

    float4* wbuf = sT[wid];
    const int rot = (lane >> 1) & 3;        // this thread's element rotation

    const int base = blockIdx.x * (TPB * TILES);

    // Warp w's element for tile k: base + k*TPB + wid*32 + lane.
    const int egi = base + (wid << 5) + lane;
    float t;
    if (FULL) t = ts[egi];
    else      t = ts[(egi < n) ? egi : (n - 1)];

    #pragma unroll 1
    for (int k = 0; k < TILES; k++) {
        // ---- Span search: j in [0,12], knots computed as m*STEPF ----
        int j = (int)(t * INV_H);
        j = max(0, min(12, j));
        j -= (j > 0)  && (t <  __int2float_rn(j)     * STEPF);
        j += (j < 12) && (t >= __int2float_rn(j + 1) * STEPF);

        // Knots around the span (interior: m*step, m clamped to [0,13]).
        const float kj0 = __int2float_rn(j)               * STEPF;
        const float km1 = __int2float_rn(max(j - 1, 0))   * STEPF;
        const float km2 = __int2float_rn(max(j - 2, 0))   * STEPF;
        const float kp1 = __int2float_rn(j + 1)           * STEPF;
        const float kp2 = __int2float_rn(min(j + 2, 13))  * STEPF;
        const float kp3 = __int2float_rn(min(j + 3, 13))  * STEPF;

        const float l1 = t - kj0;
        const float l2 = t - km1;
        const float l3 = t - km2;
        const float r1 = kp1 - t;
        const float r2 = kp2 - t;
        const float r3 = kp3 - t;

        // ---- de Boor: 4 nonzero cubic basis functions ----
        float N0 = 1.0f, N1, N2, N3, sv, tp;
        tp = __fdividef(N0, r1 + l1); N0 = r1 * tp; N1 = l1 * tp;
        tp = __fdividef(N0, r1 + l2); N0 = r1 * tp; sv = l2 * tp;
        tp = __fdividef(N1, r2 + l1); N1 = sv + r2 * tp; N2 = l1 * tp;
        tp = __fdividef(N0, r1 + l3); N0 = r1 * tp; sv = l3 * tp;
        tp = __fdividef(N1, r2 + l2); N1 = sv + r2 * tp; sv = l2 * tp;
        tp = __fdividef(N2, r3 + l1); N2 = sv + r3 * tp; N3 = l1 * tp;

        // Prefetch next tile's t.
        float tn = 0.0f;
        if (k + 1 < TILES) {
            const int gn = egi + (k + 1) * TPB;
            if (FULL) tn = ts[gn];
            else      tn = ts[(gn < n) ? gn : (n - 1)];
        }

        // ---- Build the element's 16-float row as 4 float4 slots ----
        const int jq  = j >> 2;
        const int jr  = j & 3;
        const int jq1 = (jq + 1) & 3;
        // vA = row slot jq (N shifted right by jr), vB = row slot jq+1.
        const float vA0 = (jr == 0) ? N0 : 0.f;
        const float vA1 = (jr == 0) ? N1 : (jr == 1) ? N0 : 0.f;
        const float vA2 = (jr == 0) ? N2 : (jr == 1) ? N1 : (jr == 2) ? N0 : 0.f;
        const float vA3 = (jr == 0) ? N3 : (jr == 1) ? N2 : (jr == 2) ? N1 : N0;
        const float vB0 = (jr == 1) ? N3 : (jr == 2) ? N2 : (jr == 3) ? N1 : 0.f;
        const float vB1 = (jr == 2) ? N3 : (jr == 3) ? N2 : 0.f;
        const float vB2 = (jr == 3) ? N3 : 0.f;

        // Scatter: logical slot s -> physical slot (s+rot)&3. Conflict-free.
        float4* erow = wbuf + (lane << 2);
        #pragma unroll
        for (int s = 0; s < 4; s++) {
            const bool a = (s == jq);
            const bool b = (s == jq1);
            float4 v;
            v.x = a ? vA0 : b ? vB0 : 0.f;
            v.y = a ? vA1 : b ? vB1 : 0.f;
            v.z = a ? vA2 : b ? vB2 : 0.f;
            v.w = a ? vA3 : 0.f;            // vB3 == 0
            erow[(s + rot) & 3] = v;
        }

        __syncwarp();

        // ---- Copy-out: 128 contiguous float4s, CF LDS.128 + streaming STG ----
        const int tbase4 = (base + k * TPB + (wid << 5)) * 4;  // float4 units
        float4* ob = out4 + tbase4;
        #pragma unroll
        for (int i = 0; i < 4; i++) {
            const int f  = lane + 32 * i;
            const int e  = f >> 2;
            const int c  = f & 3;
            const int re = (e >> 1) & 3;
            const float4 v = wbuf[(e << 2) + ((c + re) & 3)];
            if (FULL || tbase4 + f < n * 4)
                __stcs(&ob[f], v);
        }

        __syncwarp();   // slab reads done before next tile's scatter

        t = tn;
    }
}

extern "C" void kernel_launch(void* const* d_in, const int* in_sizes, int n_in,
                              void* d_out, int out_size)
{
    const float* ts = (const float*)d_in[0];
    float4* out4 = (float4*)d_out;
    const int n = in_sizes[0];           // 32 * 131072 = 4194304 elements
    const int epb = TPB * TILES;
    const int blocks = (n + epb - 1) / epb;
    if (n % epb == 0)
        bspline_kernel<true><<<blocks, TPB>>>(ts, out4, n);
    else
        bspline_kernel<false><<<blocks, TPB>>>(ts, out4, n);
}